// round 12
// baseline (speedup 1.0000x reference)
#include <cuda_runtime.h>
#include <cuda_fp16.h>
#include <cstdint>
#include <cstddef>

// ============================================================================
// W8Linear (harness dtypes: X f32, Wq i32, scale/bias f32, out f32).
//   Y = fp16( fp32(X @ W^T) * scale + bias ),  M=8192, K=4096, N=11008.
// Phase 1: convert W->fp16 into __device__ scratch (once).
// Phase 2: pipelined HMMA GEMM at the mma.sync ceiling (~460 TF/s):
//   M128 x N256 x K64 tiles, 256 thr (8 warps 2x4, warp tile 64x64),
//   4-stage ring: B via cp.async (fp16 scratch), A via LDG f32 -> reg
//   (3 iters ahead) -> cvt fp16 -> STS at refill. X conversion is exact
//   (x was originally fp16), so numerics identical to the R8 kernel.
// ============================================================================

#define BM 128
#define BN 256
#define BK 64
#define KSTEPS 64
#define INF 4096
#define OUTF 11008
#define MROWS 8192
#define THREADS 256
#define STAGES 4

// SMEM layout (bytes)
#define ASTAGE 16384
#define BSTAGE 32768
#define SM_A  0
#define SM_B  (STAGES * ASTAGE)                   // 65536
#define SM_SC (SM_B + STAGES * BSTAGE)            // 196608
#define SM_BI (SM_SC + 512)
#define SM_TOTAL (SM_BI + 512)                    // 197632

// fp16 W scratch (module-static device memory; not a runtime allocation)
__device__ __align__(16) __half g_Wh[(size_t)OUTF * INF];

__device__ __forceinline__ uint32_t swz(uint32_t o) { return o ^ ((o >> 3) & 0x70); }

__device__ __forceinline__ uint32_t s2u(const void* p) {
    return (uint32_t)__cvta_generic_to_shared(p);
}

__device__ __forceinline__ void cp16(uint32_t s, const void* g) {
    asm volatile("cp.async.cg.shared.global [%0], [%1], 16;" :: "r"(s), "l"(g));
}
#define CP_COMMIT() asm volatile("cp.async.commit_group;" ::: "memory")
#define CP_WAIT2()  asm volatile("cp.async.wait_group 2;" ::: "memory")

__device__ __forceinline__ void sts64(uint32_t a, uint32_t x, uint32_t y) {
    asm volatile("st.shared.v2.b32 [%0], {%1,%2};" :: "r"(a), "r"(x), "r"(y) : "memory");
}

__device__ __forceinline__ void ldsm4(uint32_t (&r)[4], uint32_t a) {
    asm volatile("ldmatrix.sync.aligned.m8n8.x4.shared.b16 {%0,%1,%2,%3}, [%4];"
                 : "=r"(r[0]), "=r"(r[1]), "=r"(r[2]), "=r"(r[3]) : "r"(a));
}

__device__ __forceinline__ void mma16816(float (&d)[4], const uint32_t (&a)[4],
                                         uint32_t b0, uint32_t b1) {
    asm volatile("mma.sync.aligned.m16n8k16.row.col.f32.f16.f16.f32 "
                 "{%0,%1,%2,%3}, {%4,%5,%6,%7}, {%8,%9}, {%0,%1,%2,%3};"
                 : "+f"(d[0]), "+f"(d[1]), "+f"(d[2]), "+f"(d[3])
                 : "r"(a[0]), "r"(a[1]), "r"(a[2]), "r"(a[3]),
                   "r"(b0), "r"(b1));
}

__device__ __forceinline__ uint32_t h2u(__half2 h) {
    return *reinterpret_cast<uint32_t*>(&h);
}

// ---- Phase 1 kernel: W int32 -> fp16 ----
__global__ void __launch_bounds__(256) cvtW_kernel(const int4* __restrict__ w,
                                                   uint2* __restrict__ o) {
    size_t i = (size_t)blockIdx.x * 256 + threadIdx.x;
    int4 v = w[i];
    uint2 r;
    r.x = h2u(__halves2half2(__int2half_rn(v.x), __int2half_rn(v.y)));
    r.y = h2u(__halves2half2(__int2half_rn(v.z), __int2half_rn(v.w)));
    o[i] = r;
}

// ---- Phase 2: GEMM ----
__global__ void __launch_bounds__(THREADS, 1)
w8lin_kernel(const float* __restrict__ X,
             const float* __restrict__ scale, const float* __restrict__ bias,
             float* __restrict__ Y)
{
    extern __shared__ char smem[];
    const uint32_t sb = s2u(smem);
    const int tid = threadIdx.x;
    const int wid = tid >> 5;
    const int lid = tid & 31;
    const int n0 = blockIdx.x * BN;
    const int m0 = blockIdx.y * BM;
    const int m_off = (wid & 1) * 64;   // 2 M-warp groups (warp tile M64)
    const int n_off = (wid >> 1) * 64;  // 4 N-warp groups (warp tile N64)

    if (tid < 256) {
        ((__half*)(smem + SM_SC))[tid] = __float2half_rn(scale[n0 + tid]);
        ((__half*)(smem + SM_BI))[tid] = __float2half_rn(bias[n0 + tid]);
    }

    // ---- A path: LDG f32 -> regs, cvt -> STS fp16 (SW128, 128 rows x 128B) ----
    // Per stage: 128 rows x 64 f32 = 2048 float4 chunks; 8 per thread.
    const int xr = tid >> 4;            // row within tile (plus +i*16 per chunk)
    const int xc = tid & 15;            // float4 column (0..15)
    float4 xreg[8];
    auto ldgX = [&](int s) {            // prefetch X(s) f32 into regs
        const float* g = X + (size_t)m0 * INF + (size_t)s * BK;
        #pragma unroll
        for (int i = 0; i < 8; i++)
            xreg[i] = *(const float4*)(g + (size_t)(xr + i * 16) * INF + xc * 4);
    };
    auto stsX = [&](int stg) {          // xreg (fp32) -> fp16 stage
        uint32_t base = sb + SM_A + (uint32_t)stg * ASTAGE;
        #pragma unroll
        for (int i = 0; i < 8; i++) {
            uint32_t h01 = h2u(__floats2half2_rn(xreg[i].x, xreg[i].y));
            uint32_t h23 = h2u(__floats2half2_rn(xreg[i].z, xreg[i].w));
            sts64(base + swz((uint32_t)((xr + i * 16) * 128 + xc * 8)), h01, h23);
        }
    };
    // ---- B: cp.async from fp16 W scratch ----
    auto loadB = [&](int s, int stg) {
        uint32_t base = sb + SM_B + (uint32_t)stg * BSTAGE;
        const __half* g = g_Wh + (size_t)n0 * INF + (size_t)s * BK;
        #pragma unroll
        for (int i = 0; i < 8; i++) {
            int idx = tid + i * THREADS;
            int r = idx >> 3, c = idx & 7;
            cp16(base + swz((uint32_t)(r * 128 + c * 16)),
                 g + (size_t)r * INF + c * 8);
        }
    };

    // ---- per-thread ldmatrix byte offsets (pre-swizzle; +kk*32 per k-step) ----
    uint32_t arow[4], brow[4];
    #pragma unroll
    for (int i = 0; i < 4; i++)
        arow[i] = (uint32_t)((m_off + i * 16 + (lid & 15)) * 128 + (lid >> 4) * 16);
    #pragma unroll
    for (int j = 0; j < 4; j++)
        brow[j] = (uint32_t)((n_off + j * 16 + ((lid >> 4) & 1) * 8 + (lid & 7)) * 128
                             + ((lid >> 3) & 1) * 16);

    float acc[4][8][4];
    #pragma unroll
    for (int i = 0; i < 4; i++)
        #pragma unroll
        for (int j = 0; j < 8; j++)
            #pragma unroll
            for (int q = 0; q < 4; q++) acc[i][j][q] = 0.0f;

    auto compute = [&](int stg) {
        uint32_t Ab = sb + SM_A + (uint32_t)stg * ASTAGE;
        uint32_t Bb = sb + SM_B + (uint32_t)stg * BSTAGE;
        #pragma unroll
        for (int kk = 0; kk < 4; kk++) {
            uint32_t a[4][4], b[4][4];
            #pragma unroll
            for (int i = 0; i < 4; i++) ldsm4(a[i], Ab + swz(arow[i] + kk * 32));
            #pragma unroll
            for (int j = 0; j < 4; j++) ldsm4(b[j], Bb + swz(brow[j] + kk * 32));
            #pragma unroll
            for (int i = 0; i < 4; i++)
                #pragma unroll
                for (int j = 0; j < 4; j++) {
                    mma16816(acc[i][2 * j],     a[i], b[j][0], b[j][1]);
                    mma16816(acc[i][2 * j + 1], a[i], b[j][2], b[j][3]);
                }
        }
    };

    // ---- prologue: A stages 0..2 direct (LDG+cvt+STS), xreg <- X(3);
    //      B stages 0..2 via cp.async (3 groups) ----
    #pragma unroll
    for (int s = 0; s < 3; s++) {
        ldgX(s); stsX(s);
        loadB(s, s); CP_COMMIT();
    }
    ldgX(3);

    // ---- mainloop: one barrier per iter (4-stage ring; refill targets the
    //      stage consumed last iter, protected by this iter's barrier) ----
    for (int s = 0; s < KSTEPS; s++) {
        CP_WAIT2();                 // B chunks of stage s complete (mine)
        __syncthreads();            // all warps' A-STS + B-chunks of stage s done
        compute(s & 3);
        if (s + 3 < KSTEPS) {       // refill (s+3)&3 == (s-1)&3 (consumed)
            stsX((s + 3) & 3);      // xreg holds X(s+3)
            loadB(s + 3, (s + 3) & 3);
        }
        if (s + 4 < KSTEPS) ldgX(s + 4);   // prefetch next A (after STS reads xreg)
        CP_COMMIT();                // keep group accounting invariant
    }

    // ---- epilogue: fp32 acc -> fp16 round -> *scale + bias (fp16) -> f32 out ----
    const int gid = lid >> 2, tig = lid & 3;
    #pragma unroll
    for (int i = 0; i < 4; i++) {
        const int rbase = m0 + m_off + i * 16 + gid;
        #pragma unroll
        for (int j = 0; j < 8; j++) {
            const int cl = n_off + j * 8 + tig * 2;
            __half2 sc = *(const __half2*)(smem + SM_SC + cl * 2);
            __half2 bi = *(const __half2*)(smem + SM_BI + cl * 2);
            __half2 h01 = __floats2half2_rn(acc[i][j][0], acc[i][j][1]);
            __half2 h23 = __floats2half2_rn(acc[i][j][2], acc[i][j][3]);
            __half2 r01 = __hadd2(__hmul2(h01, sc), bi);
            __half2 r23 = __hadd2(__hmul2(h23, sc), bi);
            *(float2*)(Y + (size_t)rbase * OUTF + n0 + cl) =
                make_float2(__low2float(r01), __high2float(r01));
            *(float2*)(Y + (size_t)(rbase + 8) * OUTF + n0 + cl) =
                make_float2(__low2float(r23), __high2float(r23));
        }
    }
}

extern "C" void kernel_launch(void* const* d_in, const int* in_sizes, int n_in,
                              void* d_out, int out_size) {
    const float* X  = (const float*)d_in[0];
    const int*   Wq = (const int*)d_in[1];
    const float* sc = (const float*)d_in[2];
    const float* bi = (const float*)d_in[3];
    float* Y = (float*)d_out;

    __half* Wh = nullptr;
    cudaGetSymbolAddress((void**)&Wh, g_Wh);

    // Phase 1: W conversion (vectorized, exact-size grid)
    cvtW_kernel<<<(unsigned)((size_t)OUTF * INF / 4 / 256), 256>>>(
        (const int4*)Wq, (uint2*)Wh);

    // Phase 2: GEMM (A converted inline from f32 X)
    static bool attr_done = false;
    if (!attr_done) {
        cudaFuncSetAttribute(w8lin_kernel,
                             cudaFuncAttributeMaxDynamicSharedMemorySize, SM_TOTAL);
        attr_done = true;
    }
    dim3 grid(OUTF / BN, MROWS / BM);   // (43, 64)
    w8lin_kernel<<<grid, THREADS, SM_TOTAL>>>(X, sc, bi, Y);
}

// round 13
// speedup vs baseline: 1.2460x; 1.2460x over previous
#include <cuda_runtime.h>
#include <cuda_fp16.h>
#include <cstdint>
#include <cstddef>

// ============================================================================
// W8Linear (harness dtypes: X f32, Wq i32, scale/bias f32, out f32).
//   Y = fp16( fp32(X @ W^T) * scale + bias ),  M=8192, K=4096, N=11008.
// Phase 1: W int32 -> int8 scratch (45MB), X f32 -> fp16 scratch (64MB).
//          Both fit L2 (109MB < 126MB); GEMM L2 read traffic 8.5GB -> 5.6GB.
// Phase 2: R8 skeleton: M128 x N256 x K64, 256 thr (8 warps 2x4, warp 64x64),
//          A via 4-stage cp.async ring; B via LDG int8 (1 iter ahead) ->
//          exact register dequant (magic-1152) -> STS fp16 at refill point.
// ============================================================================

#define BM 128
#define BN 256
#define BK 64
#define KSTEPS 64
#define INF 4096
#define OUTF 11008
#define MROWS 8192
#define THREADS 256
#define STAGES 4

// SMEM layout (bytes)
#define ASTAGE 16384
#define BSTAGE 32768
#define SM_A  0
#define SM_B  (STAGES * ASTAGE)                   // 65536
#define SM_SC (SM_B + STAGES * BSTAGE)            // 196608
#define SM_BI (SM_SC + 512)
#define SM_TOTAL (SM_BI + 512)                    // 197632

// scratch (module-static device memory; not a runtime allocation)
__device__ __align__(16) int8_t g_W8[(size_t)OUTF * INF];   // 45MB
__device__ __align__(16) __half g_Xh[(size_t)MROWS * INF];  // 64MB

__device__ __forceinline__ uint32_t swz(uint32_t o) { return o ^ ((o >> 3) & 0x70); }

__device__ __forceinline__ uint32_t s2u(const void* p) {
    return (uint32_t)__cvta_generic_to_shared(p);
}

__device__ __forceinline__ void cp16(uint32_t s, const void* g) {
    asm volatile("cp.async.cg.shared.global [%0], [%1], 16;" :: "r"(s), "l"(g));
}
#define CP_COMMIT() asm volatile("cp.async.commit_group;" ::: "memory")
#define CP_WAIT2()  asm volatile("cp.async.wait_group 2;" ::: "memory")

__device__ __forceinline__ void sts128(uint32_t a, uint32_t x, uint32_t y,
                                       uint32_t z, uint32_t w) {
    asm volatile("st.shared.v4.b32 [%0], {%1,%2,%3,%4};"
                 :: "r"(a), "r"(x), "r"(y), "r"(z), "r"(w) : "memory");
}

__device__ __forceinline__ void ldsm4(uint32_t (&r)[4], uint32_t a) {
    asm volatile("ldmatrix.sync.aligned.m8n8.x4.shared.b16 {%0,%1,%2,%3}, [%4];"
                 : "=r"(r[0]), "=r"(r[1]), "=r"(r[2]), "=r"(r[3]) : "r"(a));
}

__device__ __forceinline__ void mma16816(float (&d)[4], const uint32_t (&a)[4],
                                         uint32_t b0, uint32_t b1) {
    asm volatile("mma.sync.aligned.m16n8k16.row.col.f32.f16.f16.f32 "
                 "{%0,%1,%2,%3}, {%4,%5,%6,%7}, {%8,%9}, {%0,%1,%2,%3};"
                 : "+f"(d[0]), "+f"(d[1]), "+f"(d[2]), "+f"(d[3])
                 : "r"(a[0]), "r"(a[1]), "r"(a[2]), "r"(a[3]),
                   "r"(b0), "r"(b1));
}

__device__ __forceinline__ uint32_t h2u(__half2 h) {
    return *reinterpret_cast<uint32_t*>(&h);
}

// int8x4 -> 2x half2, exact for [-127,127] (magic 1152 trick)
__device__ __forceinline__ void dq4(uint32_t w, uint32_t& lo, uint32_t& hi) {
    w ^= 0x80808080u;
    uint32_t l = __byte_perm(w, 0x64646464u, 0x4140);
    uint32_t h = __byte_perm(w, 0x64646464u, 0x4342);
    const uint32_t MAG = 0x64806480u;  // half2(1152, 1152)
    __half2 lm = __hsub2(*reinterpret_cast<__half2*>(&l),
                         *reinterpret_cast<const __half2*>(&MAG));
    __half2 hm = __hsub2(*reinterpret_cast<__half2*>(&h),
                         *reinterpret_cast<const __half2*>(&MAG));
    lo = *reinterpret_cast<uint32_t*>(&lm);
    hi = *reinterpret_cast<uint32_t*>(&hm);
}

// ---- Phase 1 kernels ----
// W int32 -> int8 (values in [-127,127]: plain byte truncation is exact)
__global__ void __launch_bounds__(256) cvtW8_kernel(const int4* __restrict__ w,
                                                    uint4* __restrict__ o) {
    size_t i = (size_t)blockIdx.x * 256 + threadIdx.x;
    int4 a = w[4 * i], b = w[4 * i + 1], c = w[4 * i + 2], d = w[4 * i + 3];
    uint4 r;
    r.x = (a.x & 0xff) | ((a.y & 0xff) << 8) | ((a.z & 0xff) << 16) | (a.w << 24);
    r.y = (b.x & 0xff) | ((b.y & 0xff) << 8) | ((b.z & 0xff) << 16) | (b.w << 24);
    r.z = (c.x & 0xff) | ((c.y & 0xff) << 8) | ((c.z & 0xff) << 16) | (c.w << 24);
    r.w = (d.x & 0xff) | ((d.y & 0xff) << 8) | ((d.z & 0xff) << 16) | (d.w << 24);
    o[i] = r;
}
__global__ void __launch_bounds__(256) cvtX_kernel(const float4* __restrict__ x,
                                                   uint2* __restrict__ o) {
    size_t i = (size_t)blockIdx.x * 256 + threadIdx.x;
    float4 v = x[i];
    uint2 r;
    r.x = h2u(__floats2half2_rn(v.x, v.y));
    r.y = h2u(__floats2half2_rn(v.z, v.w));
    o[i] = r;
}

// ---- Phase 2: GEMM ----
__global__ void __launch_bounds__(THREADS, 1)
w8lin_kernel(const float* __restrict__ scale, const float* __restrict__ bias,
             float* __restrict__ Y)
{
    extern __shared__ char smem[];
    const uint32_t sb = s2u(smem);
    const int tid = threadIdx.x;
    const int wid = tid >> 5;
    const int lid = tid & 31;
    const int n0 = blockIdx.x * BN;
    const int m0 = blockIdx.y * BM;
    const int m_off = (wid & 1) * 64;   // 2 M-warp groups (warp tile M64)
    const int n_off = (wid >> 1) * 64;  // 4 N-warp groups (warp tile N64)

    if (tid < 256) {
        ((__half*)(smem + SM_SC))[tid] = __float2half_rn(scale[n0 + tid]);
        ((__half*)(smem + SM_BI))[tid] = __float2half_rn(bias[n0 + tid]);
    }

    // ---- A: cp.async from fp16 X scratch (SW128, 128 rows x 128B) ----
    auto loadA = [&](int s, int stg) {
        uint32_t base = sb + SM_A + (uint32_t)stg * ASTAGE;
        const __half* g = g_Xh + (size_t)m0 * INF + (size_t)s * BK;
        #pragma unroll
        for (int i = 0; i < 4; i++) {
            int idx = tid + i * THREADS;
            int r = idx >> 3, c = idx & 7;
            cp16(base + swz((uint32_t)(r * 128 + c * 16)),
                 g + (size_t)r * INF + c * 8);
        }
    };

    // ---- B: LDG int8 (one row of 64 int8 per thread) -> dequant -> STS ----
    uint4 wreg[4];
    auto ldgW8 = [&](int s) {
        const int8_t* g = g_W8 + (size_t)(n0 + tid) * INF + (size_t)s * BK;
        #pragma unroll
        for (int i = 0; i < 4; i++)
            wreg[i] = ((const uint4*)g)[i];
    };
    auto dqst = [&](int stg) {   // wreg (64 int8) -> fp16 row tid of B stage
        uint32_t base = sb + SM_B + (uint32_t)stg * BSTAGE + (uint32_t)tid * 128u;
        #pragma unroll
        for (int u = 0; u < 4; u++) {
            uint32_t a0, a1, a2, a3;
            dq4(wreg[u].x, a0, a1); dq4(wreg[u].y, a2, a3);
            sts128(sb + SM_B + (uint32_t)stg * BSTAGE
                   + swz((uint32_t)(tid * 128 + u * 32)), a0, a1, a2, a3);
            dq4(wreg[u].z, a0, a1); dq4(wreg[u].w, a2, a3);
            sts128(sb + SM_B + (uint32_t)stg * BSTAGE
                   + swz((uint32_t)(tid * 128 + u * 32 + 16)), a0, a1, a2, a3);
        }
        (void)base;
    };

    // ---- per-thread ldmatrix byte offsets (pre-swizzle; +kk*32 per k-step) ----
    uint32_t arow[4], brow[4];
    #pragma unroll
    for (int i = 0; i < 4; i++)
        arow[i] = (uint32_t)((m_off + i * 16 + (lid & 15)) * 128 + (lid >> 4) * 16);
    #pragma unroll
    for (int j = 0; j < 4; j++)
        brow[j] = (uint32_t)((n_off + j * 16 + ((lid >> 4) & 1) * 8 + (lid & 7)) * 128
                             + ((lid >> 3) & 1) * 16);

    float acc[4][8][4];
    #pragma unroll
    for (int i = 0; i < 4; i++)
        #pragma unroll
        for (int j = 0; j < 8; j++)
            #pragma unroll
            for (int q = 0; q < 4; q++) acc[i][j][q] = 0.0f;

    auto compute = [&](int stg) {
        uint32_t Ab = sb + SM_A + (uint32_t)stg * ASTAGE;
        uint32_t Bb = sb + SM_B + (uint32_t)stg * BSTAGE;
        #pragma unroll
        for (int kk = 0; kk < 4; kk++) {
            uint32_t a[4][4], b[4][4];
            #pragma unroll
            for (int i = 0; i < 4; i++) ldsm4(a[i], Ab + swz(arow[i] + kk * 32));
            #pragma unroll
            for (int j = 0; j < 4; j++) ldsm4(b[j], Bb + swz(brow[j] + kk * 32));
            #pragma unroll
            for (int i = 0; i < 4; i++)
                #pragma unroll
                for (int j = 0; j < 4; j++) {
                    mma16816(acc[i][2 * j],     a[i], b[j][0], b[j][1]);
                    mma16816(acc[i][2 * j + 1], a[i], b[j][2], b[j][3]);
                }
        }
    };

    // ---- prologue: A stages 0..2 via cp.async (3 groups); B stages 0..2
    //      dequanted in-place; wreg left holding W(3) ----
    loadA(0, 0); CP_COMMIT();
    loadA(1, 1); CP_COMMIT();
    loadA(2, 2); CP_COMMIT();
    ldgW8(0); dqst(0);
    ldgW8(1); dqst(1);
    ldgW8(2); dqst(2);
    ldgW8(3);

    // ---- mainloop: one barrier per iter (4-stage ring; refill targets stage
    //      (s-1)&3, consumed last iter and protected by this iter's barrier) ----
    for (int s = 0; s < KSTEPS; s++) {
        CP_WAIT2();                 // my A chunks of stage s complete
        __syncthreads();            // all warps' A chunks + B STS of stage s done
        compute(s & 3);
        if (s + 3 < KSTEPS) {       // refill (s+3)&3 == (s-1)&3
            loadA(s + 3, (s + 3) & 3);
            dqst((s + 3) & 3);      // wreg holds W(s+3)
        }
        if (s + 4 < KSTEPS) ldgW8(s + 4);  // prefetch after dqst consumed wreg
        CP_COMMIT();                // keep group accounting invariant
    }

    // ---- epilogue: fp32 acc -> fp16 round -> *scale + bias (fp16) -> f32 out ----
    const int gid = lid >> 2, tig = lid & 3;
    #pragma unroll
    for (int i = 0; i < 4; i++) {
        const int rbase = m0 + m_off + i * 16 + gid;
        #pragma unroll
        for (int j = 0; j < 8; j++) {
            const int cl = n_off + j * 8 + tig * 2;
            __half2 sc = *(const __half2*)(smem + SM_SC + cl * 2);
            __half2 bi = *(const __half2*)(smem + SM_BI + cl * 2);
            __half2 h01 = __floats2half2_rn(acc[i][j][0], acc[i][j][1]);
            __half2 h23 = __floats2half2_rn(acc[i][j][2], acc[i][j][3]);
            __half2 r01 = __hadd2(__hmul2(h01, sc), bi);
            __half2 r23 = __hadd2(__hmul2(h23, sc), bi);
            *(float2*)(Y + (size_t)rbase * OUTF + n0 + cl) =
                make_float2(__low2float(r01), __high2float(r01));
            *(float2*)(Y + (size_t)(rbase + 8) * OUTF + n0 + cl) =
                make_float2(__low2float(r23), __high2float(r23));
        }
    }
}

extern "C" void kernel_launch(void* const* d_in, const int* in_sizes, int n_in,
                              void* d_out, int out_size) {
    const float* X  = (const float*)d_in[0];
    const int*   Wq = (const int*)d_in[1];
    const float* sc = (const float*)d_in[2];
    const float* bi = (const float*)d_in[3];
    float* Y = (float*)d_out;

    int8_t* W8 = nullptr;
    __half* Xh = nullptr;
    cudaGetSymbolAddress((void**)&W8, g_W8);
    cudaGetSymbolAddress((void**)&Xh, g_Xh);

    // Phase 1: conversions (vectorized, exact-size grids)
    cvtW8_kernel<<<(unsigned)((size_t)OUTF * INF / 16 / 256), 256>>>(
        (const int4*)Wq, (uint4*)W8);
    cvtX_kernel<<<(unsigned)((size_t)MROWS * INF / 4 / 256), 256>>>(
        (const float4*)X, (uint2*)Xh);

    // Phase 2: GEMM
    static bool attr_done = false;
    if (!attr_done) {
        cudaFuncSetAttribute(w8lin_kernel,
                             cudaFuncAttributeMaxDynamicSharedMemorySize, SM_TOTAL);
        attr_done = true;
    }
    dim3 grid(OUTF / BN, MROWS / BM);   // (43, 64)
    w8lin_kernel<<<grid, THREADS, SM_TOTAL>>>(sc, bi, Y);
}